// round 11
// baseline (speedup 1.0000x reference)
#include <cuda_runtime.h>
#include <cuda_bf16.h>
#include <mma.h>
#include <cstdint>

using namespace nvcuda;
using bf16 = __nv_bfloat16;
#define DEV __device__ __forceinline__

static constexpr int NN = 8192;
static constexpr int FI = 256;
static constexpr int FO = 256;
static constexpr int KW = 512;    // split-W contraction dim

// shared tiling params
static constexpr int NT = 256;
static constexpr int TM = 128;
static constexpr int TN = 256;
static constexpr int S  = 3;
// bf16 GEMM1
static constexpr int KC   = 64;
static constexpr int SROW = 72;                   // elems; 144 B row
static constexpr int TA_B = TM * SROW * 2;        // 18432
static constexpr int TB_B = TN * SROW * 2;        // 36864
static constexpr int STAGE_B = TA_B + TB_B;       // 55296
// int8 GEMM2
static constexpr int KC8   = 128;                 // 128 B row
static constexpr int SROW8 = 144;                 // bytes per padded row
static constexpr int TA8   = TM * SROW8;          // 18432
static constexpr int TB8   = TN * SROW8;          // 36864
static constexpr int STAGE8 = TA8 + TB8;          // 55296
static constexpr int SMEM_SZ = S * STAGE_B;       // 165888 (same for both)
static constexpr int ECOL = 136;                  // g1 col-major epilogue ldm
static constexpr int EROW = 260;                  // g2 row-major epilogue ldm
static constexpr float SA = 63.5f;                // static A scale: (A+I) <= 2

// ---------------- scratch ----------------
__device__ float  g_dis[NN];
__device__ int8_t g_A8[(size_t)NN * NN];      // round(63.5 * (A + I))
__device__ bf16   g_X2[(size_t)NN * KW];      // [bf16(X) | bf16(X)]
__device__ bf16   g_W2[(size_t)FO * KW];      // [W_hi | W_lo]
__device__ bf16   g_Pt[(size_t)FO * NN];      // Pt[f][j] = (X W^T)^T, unscaled
__device__ int8_t g_P8[(size_t)FO * NN];      // round(sP * dis[j] * Pt[f][j])
__device__ int    g_Ci[2][(size_t)NN * FO];   // int32 split-K partials
__device__ int    g_pmax;                     // float bits of max |dis*Pt|

// ---------------- helpers ----------------
DEV uint32_t smem_u32(const void* p) {
    uint32_t a;
    asm("{ .reg .u64 t; cvta.to.shared.u64 t, %1; cvt.u32.u64 %0, t; }" : "=r"(a) : "l"(p));
    return a;
}
DEV void cp16(uint32_t s, const void* g) {
    asm volatile("cp.async.cg.shared.global [%0], [%1], 16;" :: "r"(s), "l"(g));
}
DEV void cp_commit() { asm volatile("cp.async.commit_group;" ::: "memory"); }

// ============== quant: X2 dup, W2 split; also reset g_pmax =================
__global__ void __launch_bounds__(256) k_quant(const float* __restrict__ X,
                                               const float* __restrict__ W) {
    const int bid = blockIdx.x, c = threadIdx.x;
    if (bid == 0 && c == 0) g_pmax = 0;
    if (bid < NN) {
        const bf16 v = __float2bfloat16(X[(size_t)bid * FI + c]);
        g_X2[(size_t)bid * KW + c]      = v;
        g_X2[(size_t)bid * KW + FI + c] = v;
    } else {
        const int f = bid - NN;
        const float w = W[(size_t)f * FI + c];
        const bf16 hi = __float2bfloat16(w);
        const bf16 lo = __float2bfloat16(w - __bfloat162float(hi));
        g_W2[(size_t)f * KW + c]      = hi;
        g_W2[(size_t)f * KW + FI + c] = lo;
    }
}

// ============ prep8: deg + int8(A + I), no dis dependency ==================
__global__ void __launch_bounds__(256) k_prep8(const float* __restrict__ A) {
    const int row = blockIdx.x;
    const float4* A4 = reinterpret_cast<const float4*>(A + (size_t)row * NN);
    char4* O = reinterpret_cast<char4*>(g_A8 + (size_t)row * NN);

    float sum = 0.f;
#pragma unroll
    for (int u = 0; u < 8; u++) {
        const int p4 = threadIdx.x + u * 256;
        float4 v = A4[p4];
        sum += (v.x + v.y) + (v.z + v.w);
        const int d = row - p4 * 4;
        if (d >= 0 && d < 4) {
            if      (d == 0) v.x += 1.f;
            else if (d == 1) v.y += 1.f;
            else if (d == 2) v.z += 1.f;
            else             v.w += 1.f;
        }
        char4 q;
        q.x = (char)__float2int_rn(SA * v.x);
        q.y = (char)__float2int_rn(SA * v.y);
        q.z = (char)__float2int_rn(SA * v.z);
        q.w = (char)__float2int_rn(SA * v.w);
        O[p4] = q;
    }
    __shared__ float red[256];
    red[threadIdx.x] = sum;
    __syncthreads();
#pragma unroll
    for (int off = 128; off > 0; off >>= 1) {
        if (threadIdx.x < off) red[threadIdx.x] += red[threadIdx.x + off];
        __syncthreads();
    }
    if (threadIdx.x == 0) g_dis[row] = rsqrtf(red[0] + 1.f);
}

// ============= ptmax: max over |dis[j] * Pt[f][j]| (atomic) ================
__global__ void __launch_bounds__(256) k_ptmax() {
    float m = 0.f;
    const int stride = gridDim.x * 256;
    for (size_t idx = (size_t)blockIdx.x * 256 + threadIdx.x;
         idx < (size_t)FO * NN; idx += stride) {
        const int j = (int)(idx & (NN - 1));
        const float v = fabsf(__bfloat162float(g_Pt[idx]) * g_dis[j]);
        m = fmaxf(m, v);
    }
    __shared__ float red[256];
    red[threadIdx.x] = m;
    __syncthreads();
#pragma unroll
    for (int off = 128; off > 0; off >>= 1) {
        if (threadIdx.x < off)
            red[threadIdx.x] = fmaxf(red[threadIdx.x], red[threadIdx.x + off]);
        __syncthreads();
    }
    if (threadIdx.x == 0) atomicMax(&g_pmax, __float_as_int(red[0]));
}

// ================= q8: P8 = round(sP * dis[j] * Pt) ========================
__global__ void __launch_bounds__(256) k_q8() {
    const float sP = 127.f / __int_as_float(g_pmax);
    const size_t i4 = ((size_t)blockIdx.x * 256 + threadIdx.x) * 4;
    const int j = (int)(i4 & (NN - 1));
    uint2 raw = *reinterpret_cast<const uint2*>(g_Pt + i4);
    const __nv_bfloat162 h0 = *reinterpret_cast<__nv_bfloat162*>(&raw.x);
    const __nv_bfloat162 h1 = *reinterpret_cast<__nv_bfloat162*>(&raw.y);
    char4 q;
    q.x = (char)__float2int_rn(sP * g_dis[j + 0] * __bfloat162float(h0.x));
    q.y = (char)__float2int_rn(sP * g_dis[j + 1] * __bfloat162float(h0.y));
    q.z = (char)__float2int_rn(sP * g_dis[j + 2] * __bfloat162float(h1.x));
    q.w = (char)__float2int_rn(sP * g_dis[j + 3] * __bfloat162float(h1.y));
    *reinterpret_cast<char4*>(g_P8 + i4) = q;
}

// ============= comb: out = dis_i * (C0+C1) * inv + b =======================
__global__ void __launch_bounds__(256) k_comb(float* __restrict__ out,
                                              const float* __restrict__ bias) {
    const float inv = __int_as_float(g_pmax) / (127.f * SA);
    const int t = threadIdx.x;
    const int i = blockIdx.x * 4 + (t >> 6);
    const int c4 = (t & 63) * 4;
    const size_t idx = ((size_t)i * FO + c4) / 4;
    const int4 a = reinterpret_cast<const int4*>(g_Ci[0])[idx];
    const int4 b4 = reinterpret_cast<const int4*>(g_Ci[1])[idx];
    const float4 bb = *reinterpret_cast<const float4*>(bias + c4);
    const float s = g_dis[i] * inv;
    float4 v;
    v.x = s * (float)(a.x + b4.x) + bb.x;
    v.y = s * (float)(a.y + b4.y) + bb.y;
    v.z = s * (float)(a.z + b4.z) + bb.z;
    v.w = s * (float)(a.w + b4.w) + bb.w;
    reinterpret_cast<float4*>(out)[idx] = v;
}

// ===================== GEMM1: bf16 wmma, Pt transpose ======================
template <int ROWS>
DEV void load_tile(uint32_t sdst, const bf16* __restrict__ g, int row0,
                   int ktot, int k0, int tid) {
#pragma unroll
    for (int t = 0; t < ROWS * 8 / NT; t++) {
        const int c = tid + t * NT;
        const int row = c >> 3, off = (c & 7) * 16;
        cp16(sdst + (uint32_t)(row * (SROW * 2) + off),
             reinterpret_cast<const char*>(g + (size_t)(row0 + row) * ktot + k0) + off);
    }
}

__global__ void __launch_bounds__(NT, 1)
k_g1() {
    extern __shared__ char smem[];
    const uint32_t sb = smem_u32(smem);
    const int tid = threadIdx.x, wid = tid >> 5, lid = tid & 31;
    const int wm = wid & 1, wn = wid >> 1;
    const int m0 = blockIdx.x * TM;

    wmma::fragment<wmma::accumulator, 16, 16, 16, float> acc[4][4];
#pragma unroll
    for (int i = 0; i < 4; i++)
#pragma unroll
        for (int j = 0; j < 4; j++) wmma::fill_fragment(acc[i][j], 0.f);

#pragma unroll
    for (int s = 0; s < S - 1; s++) {
        load_tile<TM>(sb + s * STAGE_B, g_X2, m0, KW, s * KC, tid);
        load_tile<TN>(sb + s * STAGE_B + TA_B, g_W2, 0, KW, s * KC, tid);
        cp_commit();
    }
    const int nk = KW / KC;
    for (int k = 0; k < nk; k++) {
        asm volatile("cp.async.wait_group 1;" ::: "memory");
        __syncthreads();
        if (k + 2 < nk) {
            const int s = (k + 2) % S;
            load_tile<TM>(sb + s * STAGE_B, g_X2, m0, KW, (k + 2) * KC, tid);
            load_tile<TN>(sb + s * STAGE_B + TA_B, g_W2, 0, KW, (k + 2) * KC, tid);
        }
        cp_commit();

        const bf16* sa  = reinterpret_cast<const bf16*>(smem + (k % S) * STAGE_B);
        const bf16* sbp = reinterpret_cast<const bf16*>(smem + (k % S) * STAGE_B + TA_B);
#pragma unroll
        for (int kk = 0; kk < KC / 16; kk++) {
            wmma::fragment<wmma::matrix_a, 16, 16, 16, bf16, wmma::row_major> fa[4];
#pragma unroll
            for (int i = 0; i < 4; i++)
                wmma::load_matrix_sync(fa[i], sa + (wm * 64 + i * 16) * SROW + kk * 16, SROW);
#pragma unroll
            for (int j = 0; j < 4; j++) {
                wmma::fragment<wmma::matrix_b, 16, 16, 16, bf16, wmma::col_major> fb;
                wmma::load_matrix_sync(fb, sbp + (wn * 64 + j * 16) * SROW + kk * 16, SROW);
#pragma unroll
                for (int i = 0; i < 4; i++)
                    wmma::mma_sync(acc[i][j], fa[i], fb, acc[i][j]);
            }
        }
    }

    __syncthreads();
    float* es = reinterpret_cast<float*>(smem);
#pragma unroll
    for (int i = 0; i < 4; i++)
#pragma unroll
        for (int j = 0; j < 4; j++)
            wmma::store_matrix_sync(es + (wm * 64 + i * 16) +
                                        (size_t)(wn * 64 + j * 16) * ECOL,
                                    acc[i][j], ECOL, wmma::mem_col_major);
    __syncthreads();
#pragma unroll
    for (int ff = 0; ff < 32; ff++) {
        const int f = wid * 32 + ff;
        const float* base = es + (size_t)f * ECOL;
#pragma unroll
        for (int half = 0; half < 2; half++) {
            const int j = half * 64 + lid * 2;
            const float2 v = *reinterpret_cast<const float2*>(base + j);
            __nv_bfloat162 h = __floats2bfloat162_rn(v.x, v.y);
            *reinterpret_cast<uint32_t*>(g_Pt + (size_t)f * NN + m0 + j) =
                *reinterpret_cast<uint32_t*>(&h);
        }
    }
}

// ===================== GEMM2: int8 wmma (IMMA) =============================
template <int ROWS>
DEV void load_tile8(uint32_t sdst, const int8_t* __restrict__ g, int row0,
                    int k0, int tid) {
#pragma unroll
    for (int t = 0; t < ROWS * 8 / NT; t++) {
        const int c = tid + t * NT;
        const int row = c >> 3, off = (c & 7) * 16;
        cp16(sdst + (uint32_t)(row * SROW8 + off),
             g + (size_t)(row0 + row) * NN + k0 + off);
    }
}

__global__ void __launch_bounds__(NT, 1)
k_g2() {
    extern __shared__ char smem[];
    const uint32_t sb = smem_u32(smem);
    const int tid = threadIdx.x, wid = tid >> 5;
    const int wm = wid & 1, wn = wid >> 1;            // 2x4 warps of 64x64
    const int m0 = blockIdx.x * TM;
    const int koff = blockIdx.z * (NN / 2);
    const int nk = (NN / 2) / KC8;                    // 32

    wmma::fragment<wmma::accumulator, 16, 16, 16, int> acc[4][4];
#pragma unroll
    for (int i = 0; i < 4; i++)
#pragma unroll
        for (int j = 0; j < 4; j++) wmma::fill_fragment(acc[i][j], 0);

#pragma unroll
    for (int s = 0; s < S - 1; s++) {
        load_tile8<TM>(sb + s * STAGE8, g_A8, m0, koff + s * KC8, tid);
        load_tile8<TN>(sb + s * STAGE8 + TA8, g_P8, 0, koff + s * KC8, tid);
        cp_commit();
    }

    for (int k = 0; k < nk; k++) {
        asm volatile("cp.async.wait_group 1;" ::: "memory");
        __syncthreads();
        if (k + 2 < nk) {
            const int s = (k + 2) % S;
            load_tile8<TM>(sb + s * STAGE8, g_A8, m0, koff + (k + 2) * KC8, tid);
            load_tile8<TN>(sb + s * STAGE8 + TA8, g_P8, 0, koff + (k + 2) * KC8, tid);
        }
        cp_commit();

        const int8_t* sa  = reinterpret_cast<const int8_t*>(smem + (k % S) * STAGE8);
        const int8_t* sbp = reinterpret_cast<const int8_t*>(smem + (k % S) * STAGE8 + TA8);
#pragma unroll
        for (int kk = 0; kk < KC8 / 16; kk++) {
            wmma::fragment<wmma::matrix_a, 16, 16, 16, signed char, wmma::row_major> fa[4];
#pragma unroll
            for (int i = 0; i < 4; i++)
                wmma::load_matrix_sync(fa[i],
                    sa + (wm * 64 + i * 16) * SROW8 + kk * 16, SROW8);
#pragma unroll
            for (int j = 0; j < 4; j++) {
                wmma::fragment<wmma::matrix_b, 16, 16, 16, signed char, wmma::col_major> fb;
                wmma::load_matrix_sync(fb,
                    sbp + (wn * 64 + j * 16) * SROW8 + kk * 16, SROW8);
#pragma unroll
                for (int i = 0; i < 4; i++)
                    wmma::mma_sync(acc[i][j], fa[i], fb, acc[i][j]);
            }
        }
    }

    // epilogue: int32 -> g_Ci[z]
    __syncthreads();
    int* es = reinterpret_cast<int*>(smem);
#pragma unroll
    for (int i = 0; i < 4; i++)
#pragma unroll
        for (int j = 0; j < 4; j++)
            wmma::store_matrix_sync(es + (size_t)(wm * 64 + i * 16) * EROW +
                                        wn * 64 + j * 16,
                                    acc[i][j], EROW, wmma::mem_row_major);
    __syncthreads();
    int* outI = g_Ci[blockIdx.z];
#pragma unroll
    for (int t = 0; t < 32; t++) {
        const int e = tid + t * NT;
        const int row = e >> 6, c4 = (e & 63) * 4;
        const int* src = es + (size_t)row * EROW + c4;
        int4 v = { src[0], src[1], src[2], src[3] };
        *reinterpret_cast<int4*>(outI + (size_t)(m0 + row) * FO + c4) = v;
    }
}

// ================================ launch ===================================
extern "C" void kernel_launch(void* const* d_in, const int* in_sizes, int n_in,
                              void* d_out, int out_size) {
    const float* X = (const float*)d_in[0];
    const float* A = (const float*)d_in[1];
    const float* W = (const float*)d_in[2];
    const float* b = (const float*)d_in[3];
    float* out = (float*)d_out;

    cudaFuncSetAttribute(k_g1, cudaFuncAttributeMaxDynamicSharedMemorySize, SMEM_SZ);
    cudaFuncSetAttribute(k_g2, cudaFuncAttributeMaxDynamicSharedMemorySize, SMEM_SZ);

    k_quant<<<NN + FO, 256>>>(X, W);                  // X2/W2 + pmax reset
    k_g1<<<NN / TM, NT, SMEM_SZ>>>();                 // Pt bf16 (unscaled)
    k_prep8<<<NN, 256>>>(A);                          // deg + A8
    k_ptmax<<<256, 256>>>();                          // max |dis*Pt|
    k_q8<<<FO * NN / 4 / 256, 256>>>();               // P8 int8
    k_g2<<<dim3(NN / TM, 1, 2), NT, SMEM_SZ>>>();     // int32 partials
    k_comb<<<NN / 4, 256>>>(out, b);                  // final scale + bias
}

// round 12
// speedup vs baseline: 3.4213x; 3.4213x over previous
#include <cuda_runtime.h>
#include <cuda.h>
#include <cuda_bf16.h>
#include <mma.h>
#include <cstdint>

using namespace nvcuda;
using bf16 = __nv_bfloat16;
#define DEV __device__ __forceinline__

static constexpr int NN = 8192;
static constexpr int FI = 256;
static constexpr int FO = 256;
static constexpr int KW = 512;

// ---------- GEMM1 (wmma + cp.async, proven) ----------
static constexpr int NT = 256;
static constexpr int TM = 128;
static constexpr int TN = 256;
static constexpr int KC = 64;
static constexpr int SROW = 72;
static constexpr int TA_B = TM * SROW * 2;
static constexpr int TB_B = TN * SROW * 2;
static constexpr int STAGE_B = TA_B + TB_B;
static constexpr int S = 3;
static constexpr int SMEM_G1 = S * STAGE_B;       // 165888
static constexpr int ECOL = 136;

// ---------- GEMM2 (TMA + ldmatrix/mma.sync) ----------
static constexpr int TM2  = 128;
static constexpr int KC2  = 64;                   // 64 bf16 = 128 B = SW128 row
static constexpr int ASZ2 = TM2 * 128;            // 16384
static constexpr int BSZ2 = FO * 128;             // 32768
static constexpr int STG2 = ASZ2 + BSZ2;          // 49152
static constexpr int SMEM_G2 = 1024 + 3 * STG2 + 1024;   // align slack

// ---------------- scratch ----------------
__device__ float g_dis[NN];
__device__ bf16  g_Abf[(size_t)NN * NN];     // bf16(A + I)
__device__ bf16  g_X2[(size_t)NN * KW];      // [dis*X | dis*X]
__device__ bf16  g_W2[(size_t)FO * KW];      // [W_hi | W_lo]
__device__ bf16  g_Pt[(size_t)FO * NN];      // Pt[f][j] (includes dis[j])
__device__ float g_C[2][(size_t)NN * FO];    // split-K partials

// ---------------- device helpers ----------------
DEV uint32_t smem_u32(const void* p) {
    uint32_t a;
    asm("{ .reg .u64 t; cvta.to.shared.u64 t, %1; cvt.u32.u64 %0, t; }" : "=r"(a) : "l"(p));
    return a;
}
DEV void cp16(uint32_t s, const void* g) {
    asm volatile("cp.async.cg.shared.global [%0], [%1], 16;" :: "r"(s), "l"(g));
}
DEV void cp_commit() { asm volatile("cp.async.commit_group;" ::: "memory"); }
DEV void mbar_init(uint32_t a, uint32_t cnt) {
    asm volatile("mbarrier.init.shared.b64 [%0], %1;" :: "r"(a), "r"(cnt) : "memory");
}
DEV void mbar_expect(uint32_t a, uint32_t bytes) {
    asm volatile("mbarrier.arrive.expect_tx.shared.b64 _, [%0], %1;"
                 :: "r"(a), "r"(bytes) : "memory");
}
DEV void mbar_wait(uint32_t a, uint32_t parity) {
    asm volatile(
        "{\n\t.reg .pred P;\n"
        "LW_%=:\n\t"
        "mbarrier.try_wait.parity.acquire.cta.shared::cta.b64 P, [%0], %1, 0x989680;\n\t"
        "@P bra LD_%=;\n\t"
        "bra LW_%=;\n"
        "LD_%=:\n\t}"
        :: "r"(a), "r"(parity) : "memory");
}
DEV void tma2d(uint32_t dst, const CUtensorMap* tm, int x, int y, uint32_t mb) {
    asm volatile(
        "cp.async.bulk.tensor.2d.shared::cta.global.tile.mbarrier::complete_tx::bytes "
        "[%0], [%1, {%2, %3}], [%4];"
        :: "r"(dst), "l"(tm), "r"(x), "r"(y), "r"(mb) : "memory");
}
DEV void ldmx4(uint32_t* t, uint32_t addr) {
    asm volatile("ldmatrix.sync.aligned.m8n8.x4.shared.b16 {%0,%1,%2,%3}, [%4];"
                 : "=r"(t[0]), "=r"(t[1]), "=r"(t[2]), "=r"(t[3]) : "r"(addr));
}
DEV void mma16816(float* d, const uint32_t* a, uint32_t b0, uint32_t b1) {
    asm volatile(
        "mma.sync.aligned.m16n8k16.row.col.f32.bf16.bf16.f32 "
        "{%0,%1,%2,%3}, {%4,%5,%6,%7}, {%8,%9}, {%0,%1,%2,%3};"
        : "+f"(d[0]), "+f"(d[1]), "+f"(d[2]), "+f"(d[3])
        : "r"(a[0]), "r"(a[1]), "r"(a[2]), "r"(a[3]), "r"(b0), "r"(b1));
}

// ========================== prep: deg + bf16(A+I) ==========================
__global__ void __launch_bounds__(256) k_prep(const float* __restrict__ A) {
    const int row = blockIdx.x;
    const float4* A4 = reinterpret_cast<const float4*>(A + (size_t)row * NN);
    uint2* O = reinterpret_cast<uint2*>(g_Abf + (size_t)row * NN);

    float sum = 0.f;
#pragma unroll
    for (int u = 0; u < 8; u++) {
        const int p4 = threadIdx.x + u * 256;
        float4 v = A4[p4];
        const int d = row - p4 * 4;
        if (d >= 0 && d < 4) {
            if      (d == 0) v.x += 1.f;
            else if (d == 1) v.y += 1.f;
            else if (d == 2) v.z += 1.f;
            else             v.w += 1.f;
        }
        sum += (v.x + v.y) + (v.z + v.w);
        __nv_bfloat162 lo = __floats2bfloat162_rn(v.x, v.y);
        __nv_bfloat162 hi = __floats2bfloat162_rn(v.z, v.w);
        uint2 st;
        st.x = *reinterpret_cast<uint32_t*>(&lo);
        st.y = *reinterpret_cast<uint32_t*>(&hi);
        O[p4] = st;
    }
    __shared__ float red[256];
    red[threadIdx.x] = sum;
    __syncthreads();
#pragma unroll
    for (int off = 128; off > 0; off >>= 1) {
        if (threadIdx.x < off) red[threadIdx.x] += red[threadIdx.x + off];
        __syncthreads();
    }
    if (threadIdx.x == 0) g_dis[row] = rsqrtf(red[0]);
}

// ============== quant: X2 = [dis*X | dis*X], W2 = [W_hi | W_lo] ============
__global__ void __launch_bounds__(256) k_quant(const float* __restrict__ X,
                                               const float* __restrict__ W) {
    const int bid = blockIdx.x, c = threadIdx.x;
    if (bid < NN) {
        const float s = g_dis[bid];
        const bf16 v = __float2bfloat16(s * X[(size_t)bid * FI + c]);
        g_X2[(size_t)bid * KW + c]      = v;
        g_X2[(size_t)bid * KW + FI + c] = v;
    } else {
        const int f = bid - NN;
        const float w = W[(size_t)f * FI + c];
        const bf16 hi = __float2bfloat16(w);
        const bf16 lo = __float2bfloat16(w - __bfloat162float(hi));
        g_W2[(size_t)f * KW + c]      = hi;
        g_W2[(size_t)f * KW + FI + c] = lo;
    }
}

// ====================== combine: out = dis*(C0+C1) + b =====================
__global__ void __launch_bounds__(256) k_comb(float* __restrict__ out,
                                              const float* __restrict__ bias) {
    const int t = threadIdx.x;
    const int i = blockIdx.x * 4 + (t >> 6);
    const int c4 = (t & 63) * 4;
    const size_t idx = ((size_t)i * FO + c4) / 4;
    const float4 a = reinterpret_cast<const float4*>(g_C[0])[idx];
    const float4 b4 = reinterpret_cast<const float4*>(g_C[1])[idx];
    const float4 bb = *reinterpret_cast<const float4*>(bias + c4);
    const float s = g_dis[i];
    float4 v;
    v.x = s * (a.x + b4.x) + bb.x;
    v.y = s * (a.y + b4.y) + bb.y;
    v.z = s * (a.z + b4.z) + bb.z;
    v.w = s * (a.w + b4.w) + bb.w;
    reinterpret_cast<float4*>(out)[idx] = v;
}

// ===================== GEMM1: bf16 wmma, Pt transpose ======================
template <int ROWS>
DEV void load_tile(uint32_t sdst, const bf16* __restrict__ g, int row0,
                   int ktot, int k0, int tid) {
#pragma unroll
    for (int t = 0; t < ROWS * 8 / NT; t++) {
        const int c = tid + t * NT;
        const int row = c >> 3, off = (c & 7) * 16;
        cp16(sdst + (uint32_t)(row * (SROW * 2) + off),
             reinterpret_cast<const char*>(g + (size_t)(row0 + row) * ktot + k0) + off);
    }
}

__global__ void __launch_bounds__(NT, 1)
k_g1() {
    extern __shared__ char smem[];
    const uint32_t sb = smem_u32(smem);
    const int tid = threadIdx.x, wid = tid >> 5, lid = tid & 31;
    const int wm = wid & 1, wn = wid >> 1;
    const int m0 = blockIdx.x * TM;

    wmma::fragment<wmma::accumulator, 16, 16, 16, float> acc[4][4];
#pragma unroll
    for (int i = 0; i < 4; i++)
#pragma unroll
        for (int j = 0; j < 4; j++) wmma::fill_fragment(acc[i][j], 0.f);

#pragma unroll
    for (int s = 0; s < S - 1; s++) {
        load_tile<TM>(sb + s * STAGE_B, g_X2, m0, KW, s * KC, tid);
        load_tile<TN>(sb + s * STAGE_B + TA_B, g_W2, 0, KW, s * KC, tid);
        cp_commit();
    }
    const int nk = KW / KC;
    for (int k = 0; k < nk; k++) {
        asm volatile("cp.async.wait_group 1;" ::: "memory");
        __syncthreads();
        if (k + 2 < nk) {
            const int s = (k + 2) % S;
            load_tile<TM>(sb + s * STAGE_B, g_X2, m0, KW, (k + 2) * KC, tid);
            load_tile<TN>(sb + s * STAGE_B + TA_B, g_W2, 0, KW, (k + 2) * KC, tid);
        }
        cp_commit();

        const bf16* sa  = reinterpret_cast<const bf16*>(smem + (k % S) * STAGE_B);
        const bf16* sbp = reinterpret_cast<const bf16*>(smem + (k % S) * STAGE_B + TA_B);
#pragma unroll
        for (int kk = 0; kk < KC / 16; kk++) {
            wmma::fragment<wmma::matrix_a, 16, 16, 16, bf16, wmma::row_major> fa[4];
#pragma unroll
            for (int i = 0; i < 4; i++)
                wmma::load_matrix_sync(fa[i], sa + (wm * 64 + i * 16) * SROW + kk * 16, SROW);
#pragma unroll
            for (int j = 0; j < 4; j++) {
                wmma::fragment<wmma::matrix_b, 16, 16, 16, bf16, wmma::col_major> fb;
                wmma::load_matrix_sync(fb, sbp + (wn * 64 + j * 16) * SROW + kk * 16, SROW);
#pragma unroll
                for (int i = 0; i < 4; i++)
                    wmma::mma_sync(acc[i][j], fa[i], fb, acc[i][j]);
            }
        }
    }

    __syncthreads();
    float* es = reinterpret_cast<float*>(smem);
#pragma unroll
    for (int i = 0; i < 4; i++)
#pragma unroll
        for (int j = 0; j < 4; j++)
            wmma::store_matrix_sync(es + (wm * 64 + i * 16) +
                                        (size_t)(wn * 64 + j * 16) * ECOL,
                                    acc[i][j], ECOL, wmma::mem_col_major);
    __syncthreads();
#pragma unroll
    for (int ff = 0; ff < 32; ff++) {
        const int f = wid * 32 + ff;
        const float* base = es + (size_t)f * ECOL;
#pragma unroll
        for (int half = 0; half < 2; half++) {
            const int j = half * 64 + lid * 2;
            const float2 v = *reinterpret_cast<const float2*>(base + j);
            __nv_bfloat162 h = __floats2bfloat162_rn(v.x, v.y);
            *reinterpret_cast<uint32_t*>(g_Pt + (size_t)f * NN + m0 + j) =
                *reinterpret_cast<uint32_t*>(&h);
        }
    }
}

// ============== GEMM2: TMA + swizzled ldmatrix + mma.sync ==================
__global__ void __launch_bounds__(256, 1)
k_g2(const __grid_constant__ CUtensorMap tmA,
     const __grid_constant__ CUtensorMap tmB) {
    extern __shared__ char dsm[];
    __shared__ uint64_t mbars[3];
    const uint32_t base = (smem_u32(dsm) + 1023u) & ~1023u;
    const uint32_t mb = smem_u32(mbars);
    const int tid = threadIdx.x, lane = tid & 31, wid = tid >> 5;
    const int wm = wid & 1, wn = wid >> 1;            // 2x4 warps of 64x64
    const int m0 = blockIdx.x * TM2;
    const int kbase = blockIdx.z * (NN / 2);
    const int nk = (NN / 2) / KC2;                    // 64

    if (tid == 0) { mbar_init(mb, 1); mbar_init(mb + 8, 1); mbar_init(mb + 16, 1); }
    __syncthreads();

    float acc[4][8][4];
#pragma unroll
    for (int i = 0; i < 4; i++)
#pragma unroll
        for (int j = 0; j < 8; j++)
#pragma unroll
            for (int e = 0; e < 4; e++) acc[i][j][e] = 0.f;

    if (tid == 0) {
#pragma unroll
        for (int s = 0; s < 2; s++) {
            mbar_expect(mb + s * 8, STG2);
            tma2d(base + s * STG2, &tmA, kbase + s * KC2, m0, mb + s * 8);
            tma2d(base + s * STG2 + ASZ2, &tmB, kbase + s * KC2, 0, mb + s * 8);
        }
    }

    const int r15 = lane & 15, ch = lane >> 4;
    const int sw = r15 & 7;                           // swizzle sel (same A/B)
    const int atomA0 = (wm * 64 + r15) >> 3;          // +2 per i
    const int atomB0 = (wn * 64 + r15) >> 3;          // +2 per jj

    for (int k = 0; k < nk; k++) {
        __syncthreads();                               // stage (k-1)%3 consumed
        if (tid == 0 && k + 2 < nk) {
            const int s = (k + 2) % 3;
            mbar_expect(mb + s * 8, STG2);
            tma2d(base + s * STG2, &tmA, kbase + (k + 2) * KC2, m0, mb + s * 8);
            tma2d(base + s * STG2 + ASZ2, &tmB, kbase + (k + 2) * KC2, 0, mb + s * 8);
        }
        mbar_wait(mb + (k % 3) * 8, (k / 3) & 1);

        const uint32_t sa  = base + (k % 3) * STG2;
        const uint32_t sbB = sa + ASZ2;
#pragma unroll
        for (int kk = 0; kk < 4; kk++) {
            const int chunk = kk * 2 + ch;
            const uint32_t csw = (uint32_t)((chunk ^ sw) << 4) + (uint32_t)(sw << 7);
            uint32_t a[4][4];
#pragma unroll
            for (int i = 0; i < 4; i++)
                ldmx4(a[i], sa + ((uint32_t)(atomA0 + 2 * i) << 10) + csw);
#pragma unroll
            for (int jj = 0; jj < 4; jj++) {
                uint32_t t[4];
                ldmx4(t, sbB + ((uint32_t)(atomB0 + 2 * jj) << 10) + csw);
#pragma unroll
                for (int i = 0; i < 4; i++) {
                    mma16816(acc[i][2 * jj],     a[i], t[0], t[2]);
                    mma16816(acc[i][2 * jj + 1], a[i], t[1], t[3]);
                }
            }
        }
    }

    // epilogue: direct fp32 stores
    float* outF = g_C[blockIdx.z];
    const int rb = m0 + wm * 64 + (lane >> 2);
    const int cb = wn * 64 + (lane & 3) * 2;
#pragma unroll
    for (int i = 0; i < 4; i++)
#pragma unroll
        for (int jn = 0; jn < 8; jn++) {
            const int r = rb + i * 16, c = cb + jn * 8;
            *reinterpret_cast<float2*>(&outF[(size_t)r * FO + c]) =
                make_float2(acc[i][jn][0], acc[i][jn][1]);
            *reinterpret_cast<float2*>(&outF[(size_t)(r + 8) * FO + c]) =
                make_float2(acc[i][jn][2], acc[i][jn][3]);
        }
}

// ========================= host: tensormap encode ==========================
typedef CUresult (*EncodeFn)(CUtensorMap*, CUtensorMapDataType, cuuint32_t, void*,
                             const cuuint64_t*, const cuuint64_t*, const cuuint32_t*,
                             const cuuint32_t*, CUtensorMapInterleave, CUtensorMapSwizzle,
                             CUtensorMapL2promotion, CUtensorMapFloatOOBfill);

static void encode_bf16_2d(CUtensorMap* tm, void* ptr, uint64_t cols, uint64_t rows,
                           uint32_t box0, uint32_t box1) {
    EncodeFn fn = nullptr;
    cudaDriverEntryPointQueryResult qr;
#if CUDART_VERSION >= 12050
    cudaGetDriverEntryPointByVersion("cuTensorMapEncodeTiled", (void**)&fn, 12000,
                                     cudaEnableDefault, &qr);
#else
    cudaGetDriverEntryPoint("cuTensorMapEncodeTiled", (void**)&fn,
                            cudaEnableDefault, &qr);
#endif
    cuuint64_t dims[2] = {cols, rows};
    cuuint64_t strides[1] = {cols * 2};
    cuuint32_t box[2] = {box0, box1};
    cuuint32_t es[2] = {1, 1};
    fn(tm, CU_TENSOR_MAP_DATA_TYPE_BFLOAT16, 2, ptr, dims, strides, box, es,
       CU_TENSOR_MAP_INTERLEAVE_NONE, CU_TENSOR_MAP_SWIZZLE_128B,
       CU_TENSOR_MAP_L2_PROMOTION_L2_128B, CU_TENSOR_MAP_FLOAT_OOB_FILL_NONE);
}

// ================================ launch ===================================
extern "C" void kernel_launch(void* const* d_in, const int* in_sizes, int n_in,
                              void* d_out, int out_size) {
    const float* X = (const float*)d_in[0];
    const float* A = (const float*)d_in[1];
    const float* W = (const float*)d_in[2];
    const float* b = (const float*)d_in[3];
    float* out = (float*)d_out;

    cudaFuncSetAttribute(k_g1, cudaFuncAttributeMaxDynamicSharedMemorySize, SMEM_G1);
    cudaFuncSetAttribute(k_g2, cudaFuncAttributeMaxDynamicSharedMemorySize, SMEM_G2);

    bf16 *Abf, *Pt;
    cudaGetSymbolAddress((void**)&Abf, g_Abf);
    cudaGetSymbolAddress((void**)&Pt,  g_Pt);

    CUtensorMap tmA, tmB;
    encode_bf16_2d(&tmA, Abf, NN, NN, KC2, TM2);   // box 64x128
    encode_bf16_2d(&tmB, Pt,  NN, FO, KC2, FO);    // box 64x256

    k_prep<<<NN, 256>>>(A);
    k_quant<<<NN + FO, 256>>>(X, W);
    k_g1<<<NN / TM, NT, SMEM_G1>>>();
    k_g2<<<dim3(NN / TM2, 1, 2), 256, SMEM_G2>>>(tmA, tmB);
    k_comb<<<NN / 4, 256>>>(out, b);
}